// round 12
// baseline (speedup 1.0000x reference)
#include <cuda_runtime.h>
#include <cuda_fp16.h>
#include <cuda_bf16.h>
#include <math.h>

// Problem constants (B=1, L=4096, DM=1024, NH=16, DH=64, w=512, C=8)
#define L_TOK   4096
#define DMODEL  1024
#define DHEAD   64
#define WCHUNK  512
#define NCHUNK  8
#define NKEY    1536                 // 3*w effective keys (z-sum collapses chunks)
#define NQROW   65536                // L * NH query rows of dim 64
#define NSPLIT  4                    // split-K factor for the kvp GEMM

#define LOG2E   1.4426950408889634f

// -------------------- scratch (no cudaMalloc allowed) --------------------
__device__ __half g_qh  [L_TOK * DMODEL];             // fp16 q
__device__ __half g_kvh [L_TOK * DMODEL];             // fp16 kv
__device__ __half g_WqT [DMODEL * DMODEL];            // fp16 Wq^T  [N][K]
__device__ __half g_WkvT[2 * DHEAD * DMODEL];         // fp16 Wkv^T [N][K]
__device__ __half g_WcT [DMODEL * DMODEL];            // fp16 Wc^T  [N][K]
__device__ __half g_qph [NQROW * DHEAD];              // qp fp16 (pre-scaled log2e)
__device__ float  g_kvp [NSPLIT * L_TOK * 2 * DHEAD]; // split-K partials
__device__ __half g_keff[NKEY * DHEAD];               // fp16 [key][dim]
__device__ __half g_vt  [DHEAD * NKEY];               // fp16 transposed [dim][key]
__device__ __half g_ctxh[NQROW * DHEAD];              // attention output fp16

// -------------------- helpers --------------------
__device__ __forceinline__ float ex2f(float x) {
    float y;
    asm("ex2.approx.ftz.f32 %0, %1;" : "=f"(y) : "f"(x));
    return y;
}
__device__ __forceinline__ unsigned h2_as_u32(__half2 h) {
    return *reinterpret_cast<unsigned*>(&h);
}

__device__ __forceinline__ void mma_f16(float* c, const unsigned* a,
                                        unsigned b0, unsigned b1) {
    asm volatile(
        "mma.sync.aligned.m16n8k16.row.col.f32.f16.f16.f32 "
        "{%0,%1,%2,%3},{%4,%5,%6,%7},{%8,%9},{%0,%1,%2,%3};"
        : "+f"(c[0]), "+f"(c[1]), "+f"(c[2]), "+f"(c[3])
        : "r"(a[0]), "r"(a[1]), "r"(a[2]), "r"(a[3]), "r"(b0), "r"(b1));
}

__device__ __forceinline__ void cp_async16(void* smem_dst, const void* gmem_src) {
    unsigned s = (unsigned)__cvta_generic_to_shared(smem_dst);
    asm volatile("cp.async.ca.shared.global [%0], [%1], 16;\n"
                 :: "r"(s), "l"(gmem_src));
}
__device__ __forceinline__ void cp_commit() {
    asm volatile("cp.async.commit_group;\n" ::: "memory");
}

// -------------------- prepass: fp32 -> fp16 (two tensors, one launch) -----
__global__ void to_half_dual(const float* __restrict__ a,
                             const float* __restrict__ b,
                             __half* __restrict__ oa, __half* __restrict__ ob,
                             int n)
{
    int i = (blockIdx.x * blockDim.x + threadIdx.x) * 4;
    const float* src;
    __half* dst;
    if (i < n) { src = a + i; dst = oa + i; }
    else {
        int k = i - n;
        if (k >= n) return;
        src = b + k; dst = ob + k;
    }
    float4 v = *(const float4*)src;
    *(__half2*)(dst)     = __floats2half2_rn(v.x, v.y);
    *(__half2*)(dst + 2) = __floats2half2_rn(v.z, v.w);
}

// -------------------- prepass: transpose + fp16 (W [R][C] -> WT [C][R]) ---
__global__ void transpose_h(const float* __restrict__ W, __half* __restrict__ WT,
                            int R, int C)
{
    __shared__ float t[32][33];
    int cb = blockIdx.x * 32, rb = blockIdx.y * 32;
    int tx = threadIdx.x, ty = threadIdx.y;     // 32 x 8
#pragma unroll
    for (int j = 0; j < 32; j += 8)
        t[ty + j][tx] = W[(size_t)(rb + ty + j) * C + cb + tx];
    __syncthreads();
#pragma unroll
    for (int j = 0; j < 32; j += 8)
        WT[(size_t)(cb + ty + j) * R + rb + tx] = __float2half_rn(t[tx][ty + j]);
}

// -------------------- FP16 tensor-core GEMM ------------------------------
// C = alpha * A(M x Klen) B^T-slice, A fp16 [M][Kfull] row-major,
// B fp16 [N][Kfull] (pre-transposed weights). 128x128 block tile, BK=64,
// 4 warps (2x2), 64x64 warp tile. Stride-72 smem, conflict-free b32 frag
// loads. 2-stage cp.async. blockIdx.z = split-K slice; C offset z*M*N.
// OUT: 0 = fp32 C, 2 = fp16 C.
#define SA 72
#define GF16_STAGE (128 * SA)                 // halves per operand stage
#define GF16_SMEM_BYTES (4 * GF16_STAGE * 2)  // 73728 B

template<int OUT>
__global__ __launch_bounds__(128, 2) void gemm_f16(
    const __half* __restrict__ A, const __half* __restrict__ B,
    void* __restrict__ Cv, int M, int N, int Kfull, int Klen, float alpha)
{
    extern __shared__ __half smh[];
    __half* AsBuf = smh;                      // 2 x [128][SA]
    __half* BsBuf = smh + 2 * GF16_STAGE;     // 2 x [128][SA]

    const int tid  = threadIdx.x;
    const int lane = tid & 31;
    const int warp = tid >> 5;
    const int wm = warp >> 1;        // 0..1
    const int wn = warp & 1;         // 0..1
    const int bm = blockIdx.y * 128;
    const int bn = blockIdx.x * 128;
    const int qr = lane >> 2;        // 0..7
    const int qc = lane & 3;         // 0..3
    const int Kstart = blockIdx.z * Klen;

    const __half* Ab = A + (size_t)bm * Kfull + Kstart;
    const __half* Bb = B + (size_t)bn * Kfull + Kstart;

    auto issue = [&](int kt, int stage) {
        const __half* Ag = Ab + kt * 64;
        const __half* Bg = Bb + kt * 64;
        __half* Asd = AsBuf + stage * GF16_STAGE;
        __half* Bsd = BsBuf + stage * GF16_STAGE;
#pragma unroll
        for (int i = 0; i < 8; i++) {          // 128 rows x 8 x 16B each op
            int idx = tid + i * 128;
            int r = idx >> 3, c8 = (idx & 7) * 8;
            cp_async16(Asd + r * SA + c8, Ag + (size_t)r * Kfull + c8);
            cp_async16(Bsd + r * SA + c8, Bg + (size_t)r * Kfull + c8);
        }
        cp_commit();
    };

    float acc[4][8][4];
#pragma unroll
    for (int mt = 0; mt < 4; mt++)
#pragma unroll
        for (int nt = 0; nt < 8; nt++)
#pragma unroll
            for (int i = 0; i < 4; i++) acc[mt][nt][i] = 0.f;

    const int NK = Klen / 64;
    issue(0, 0);
    for (int kt = 0; kt < NK; ++kt) {
        if (kt + 1 < NK) {
            issue(kt + 1, (kt + 1) & 1);
            asm volatile("cp.async.wait_group 1;\n" ::: "memory");
        } else {
            asm volatile("cp.async.wait_group 0;\n" ::: "memory");
        }
        __syncthreads();
        const __half* As = AsBuf + (kt & 1) * GF16_STAGE;
        const __half* Bs = BsBuf + (kt & 1) * GF16_STAGE;

#pragma unroll
        for (int ck = 0; ck < 4; ++ck) {       // 4 k16 chunks per BK=64
            const int k0 = ck * 16 + 2 * qc;
            unsigned a[4][4];
#pragma unroll
            for (int mt = 0; mt < 4; ++mt) {
                const __half* ar = As + (wm * 64 + mt * 16 + qr) * SA + k0;
                a[mt][0] = *(const unsigned*)(ar);
                a[mt][1] = *(const unsigned*)(ar + 8 * SA);
                a[mt][2] = *(const unsigned*)(ar + 8);
                a[mt][3] = *(const unsigned*)(ar + 8 * SA + 8);
            }
#pragma unroll
            for (int nt = 0; nt < 8; ++nt) {
                const __half* br = Bs + (wn * 64 + nt * 8 + qr) * SA + k0;
                unsigned b0 = *(const unsigned*)(br);
                unsigned b1 = *(const unsigned*)(br + 8);
#pragma unroll
                for (int mt = 0; mt < 4; ++mt)
                    mma_f16(acc[mt][nt], a[mt], b0, b1);
            }
        }
        __syncthreads();
    }

#pragma unroll
    for (int mt = 0; mt < 4; ++mt) {
#pragma unroll
        for (int nt = 0; nt < 8; ++nt) {
            int r = bm + wm * 64 + mt * 16 + qr;
            int c = bn + wn * 64 + nt * 8 + qc * 2;
            float v0 = alpha * acc[mt][nt][0];
            float v1 = alpha * acc[mt][nt][1];
            float v2 = alpha * acc[mt][nt][2];
            float v3 = alpha * acc[mt][nt][3];
            if (OUT == 2) {
                __half* Ch = (__half*)Cv + (size_t)blockIdx.z * M * N;
                *(__half2*)&Ch[(size_t)r * N + c] = __floats2half2_rn(v0, v1);
                *(__half2*)&Ch[(size_t)(r + 8) * N + c] = __floats2half2_rn(v2, v3);
            } else {
                float* Cf = (float*)Cv + (size_t)blockIdx.z * M * N;
                *(float2*)&Cf[(size_t)r * N + c] = make_float2(v0, v1);
                *(float2*)&Cf[(size_t)(r + 8) * N + c] = make_float2(v2, v3);
            }
        }
    }
}

// -------------------- build K_eff / V_eff^T (fp16, sums split-K partials) -
__global__ void build_eff(const float* __restrict__ kvp,
                          __half* __restrict__ keff, __half* __restrict__ vt)
{
    int idx = blockIdx.x * blockDim.x + threadIdx.x;
    if (idx >= WCHUNK * DHEAD) return;
    int y = idx >> 6;
    int d = idx & 63;

    float ks = 0.f, vs = 0.f, kf = 0.f, vf = 0.f, kl = 0.f, vl = 0.f;
#pragma unroll
    for (int c = 0; c < NCHUNK; c++) {
        float kx = 0.f, vx = 0.f;
#pragma unroll
        for (int s = 0; s < NSPLIT; s++) {
            const float* row = kvp + (size_t)s * L_TOK * 2 * DHEAD
                             + (size_t)((c << 9) + y) * (2 * DHEAD);
            kx += row[d];
            vx += row[DHEAD + d];
        }
        if (c == 0)          { kf = kx; vf = vx; }
        if (c == NCHUNK - 1) { kl = kx; vl = vx; }
        ks += kx; vs += vx;
    }
    // K_eff fp16 [e*512+y][d]; V_eff^T fp16 [d][e*512+y]
    keff[(0 * WCHUNK + y) * DHEAD + d] = __float2half_rn(ks - kl);
    keff[(1 * WCHUNK + y) * DHEAD + d] = __float2half_rn(ks);
    keff[(2 * WCHUNK + y) * DHEAD + d] = __float2half_rn(ks - kf);
    vt[(size_t)d * NKEY + 0 * WCHUNK + y] = __float2half_rn(vs - vl);
    vt[(size_t)d * NKEY + 1 * WCHUNK + y] = __float2half_rn(vs);
    vt[(size_t)d * NKEY + 2 * WCHUNK + y] = __float2half_rn(vs - vf);
}

// -------------------- FP16 flash attention --------------------------------
// 128 query rows / block (4 warps x 32 rows = 2 m-tiles of 16). Grid 512.
// K/V tiles of 64 keys in fp16 smem (stride 72, conflict-free), cp.async
// double-buffered. Fused per-16-key chunk: S-mma -> exp -> PV-mma, so the
// MUFU exp of chunk j overlaps the tensor S-mma of chunk j+1 (pipes were
// phase-serialized before: tensor stuck at 56%). l computed exactly by an
// extra ones-column MMA (P x 1 = rowsum), removing all l FADDs + shuffles.
// No online max (scores bounded); Q pre-scaled by log2e -> bare ex2.approx.
#define SH 72                                   // smem stride in halves
#define AT_STAGE_H (2 * 64 * SH)                // K + Vt per stage (halves)
#define ATTN_SMEM_BYTES (2 * AT_STAGE_H * 2)    // 36864 B
#define NKT (NKEY / 64)                         // 24
#define ONE2 0x3C003C00u                        // half2(1.0, 1.0)

__global__ __launch_bounds__(128, 3) void attn_fp16(
    const __half* __restrict__ Q, const __half* __restrict__ Ke,
    const __half* __restrict__ Vt, __half* __restrict__ O)
{
    extern __shared__ __half smh[];
    const int tid  = threadIdx.x;
    const int lane = tid & 31;
    const int warp = tid >> 5;       // 0..3
    const int qr = lane >> 2;        // 0..7
    const int qc = lane & 3;         // 0..3
    const int qbase = blockIdx.x * 128;
    const int row0 = warp * 32 + qr; // +mt*16; +8 for c2/c3

    auto issueKV = [&](int kt, int stage) {
        const __half* Kg = Ke + (size_t)(kt * 64) * DHEAD;   // [key][64]
        const __half* Vg = Vt + kt * 64;                     // [dim][NKEY]
        __half* Kd = smh + stage * AT_STAGE_H;
        __half* Vd = Kd + 64 * SH;
#pragma unroll
        for (int i = 0; i < 4; i++) {          // 64 rows x 8 chunks each
            int idx = tid + i * 128;
            int r = idx >> 3, c8 = (idx & 7) * 8;
            cp_async16(Kd + r * SH + c8, Kg + r * DHEAD + c8);
            cp_async16(Vd + r * SH + c8, Vg + (size_t)r * NKEY + c8);
        }
        cp_commit();
    };

    // Q A-fragments for both m-tiles: 4 k16-chunks, 4 b32 each (fp16 pairs)
    unsigned aq[2][4][4];
#pragma unroll
    for (int mt = 0; mt < 2; mt++) {
        const __half* q0 = Q + (size_t)(qbase + row0 + mt * 16) * DHEAD;
        const __half* q8 = q0 + 8 * DHEAD;
#pragma unroll
        for (int kk = 0; kk < 4; kk++) {
            int c = kk * 16 + 2 * qc;
            aq[mt][kk][0] = *(const unsigned*)(q0 + c);
            aq[mt][kk][1] = *(const unsigned*)(q8 + c);
            aq[mt][kk][2] = *(const unsigned*)(q0 + c + 8);
            aq[mt][kk][3] = *(const unsigned*)(q8 + c + 8);
        }
    }

    float oacc[2][8][4];
    float ol[2][4];                  // ones-column accumulators (row sums l)
#pragma unroll
    for (int mt = 0; mt < 2; mt++) {
#pragma unroll
        for (int n = 0; n < 8; n++)
#pragma unroll
            for (int i = 0; i < 4; i++) oacc[mt][n][i] = 0.f;
#pragma unroll
        for (int i = 0; i < 4; i++) ol[mt][i] = 0.f;
    }

    issueKV(0, 0);
    for (int kt = 0; kt < NKT; ++kt) {
        if (kt + 1 < NKT) {
            issueKV(kt + 1, (kt + 1) & 1);
            asm volatile("cp.async.wait_group 1;\n" ::: "memory");
        } else {
            asm volatile("cp.async.wait_group 0;\n" ::: "memory");
        }
        __syncthreads();
        const __half* Ks = smh + (kt & 1) * AT_STAGE_H;
        const __half* Vs = Ks + 64 * SH;

        // Fused per-16-key chunk: S-mma -> exp -> PV-mma.
#pragma unroll
        for (int j = 0; j < 4; ++j) {
            // ---- S = Q K^T for key n-tiles 2j, 2j+1 ----
            float p[2][2][4];
#pragma unroll
            for (int mt = 0; mt < 2; mt++)
#pragma unroll
                for (int t = 0; t < 2; t++)
#pragma unroll
                    for (int i = 0; i < 4; i++) p[mt][t][i] = 0.f;
#pragma unroll
            for (int kk = 0; kk < 4; ++kk) {
#pragma unroll
                for (int t = 0; t < 2; ++t) {
                    const __half* kr =
                        Ks + ((2 * j + t) * 8 + qr) * SH + kk * 16 + 2 * qc;
                    unsigned b0 = *(const unsigned*)(kr);
                    unsigned b1 = *(const unsigned*)(kr + 8);
                    mma_f16(p[0][t], aq[0][kk], b0, b1);
                    mma_f16(p[1][t], aq[1][kk], b0, b1);
                }
            }

            // ---- exp2 + pack straight into PV A-frags ----
            unsigned pa[2][4];
#pragma unroll
            for (int mt = 0; mt < 2; mt++)
#pragma unroll
                for (int t = 0; t < 2; t++) {
                    float e0 = ex2f(p[mt][t][0]);
                    float e1 = ex2f(p[mt][t][1]);
                    float e2 = ex2f(p[mt][t][2]);
                    float e3 = ex2f(p[mt][t][3]);
                    pa[mt][2 * t]     = h2_as_u32(__floats2half2_rn(e0, e1));
                    pa[mt][2 * t + 1] = h2_as_u32(__floats2half2_rn(e2, e3));
                }

            // ---- l += P x ones (exact rowsum of the half P used below) ----
            mma_f16(ol[0], pa[0], ONE2, ONE2);
            mma_f16(ol[1], pa[1], ONE2, ONE2);

            // ---- O += P V for this 16-key chunk ----
#pragma unroll
            for (int n = 0; n < 8; ++n) {
                const __half* vr = Vs + (n * 8 + qr) * SH + j * 16 + 2 * qc;
                unsigned b0 = *(const unsigned*)(vr);
                unsigned b1 = *(const unsigned*)(vr + 8);
                mma_f16(oacc[0][n], pa[0], b0, b1);
                mma_f16(oacc[1][n], pa[1], b0, b1);
            }
        }
        __syncthreads();
    }

    // ---- finalize: l exact in ol (c0=row r, c2=row r+8); O / l, fp16 ----
#pragma unroll
    for (int mt = 0; mt < 2; mt++) {
        float inv0 = 1.f / ol[mt][0];
        float inv1 = 1.f / ol[mt][2];
        const int r = qbase + row0 + mt * 16;
#pragma unroll
        for (int n = 0; n < 8; ++n) {
            int c = n * 8 + qc * 2;
            *(__half2*)&O[(size_t)r * DHEAD + c] =
                __floats2half2_rn(oacc[mt][n][0] * inv0, oacc[mt][n][1] * inv0);
            *(__half2*)&O[(size_t)(r + 8) * DHEAD + c] =
                __floats2half2_rn(oacc[mt][n][2] * inv1, oacc[mt][n][3] * inv1);
        }
    }
}

// -------------------- launch --------------------
extern "C" void kernel_launch(void* const* d_in, const int* in_sizes, int n_in,
                              void* d_out, int out_size)
{
    const float* q   = (const float*)d_in[0];
    const float* kv  = (const float*)d_in[1];
    const float* Wq  = (const float*)d_in[2];
    const float* Wkv = (const float*)d_in[3];
    const float* Wc  = (const float*)d_in[4];
    float* out = (float*)d_out;

    __half *qh, *kvh, *WqT, *WkvT, *WcT, *qph, *keff, *vt, *ctxh;
    float *kvp;
    cudaGetSymbolAddress((void**)&qh,   g_qh);
    cudaGetSymbolAddress((void**)&kvh,  g_kvh);
    cudaGetSymbolAddress((void**)&WqT,  g_WqT);
    cudaGetSymbolAddress((void**)&WkvT, g_WkvT);
    cudaGetSymbolAddress((void**)&WcT,  g_WcT);
    cudaGetSymbolAddress((void**)&qph,  g_qph);
    cudaGetSymbolAddress((void**)&kvp,  g_kvp);
    cudaGetSymbolAddress((void**)&keff, g_keff);
    cudaGetSymbolAddress((void**)&vt,   g_vt);
    cudaGetSymbolAddress((void**)&ctxh, g_ctxh);

    cudaFuncSetAttribute(gemm_f16<0>,
                         cudaFuncAttributeMaxDynamicSharedMemorySize,
                         GF16_SMEM_BYTES);
    cudaFuncSetAttribute(gemm_f16<2>,
                         cudaFuncAttributeMaxDynamicSharedMemorySize,
                         GF16_SMEM_BYTES);
    cudaFuncSetAttribute(attn_fp16,
                         cudaFuncAttributeMaxDynamicSharedMemorySize,
                         ATTN_SMEM_BYTES);

    // prepass: activations to fp16 (one launch); weights transposed+fp16
    to_half_dual<<<8192, 256>>>(q, kv, qh, kvh, L_TOK * DMODEL);
    transpose_h<<<dim3(32, 32), dim3(32, 8)>>>(Wq,  WqT,  DMODEL, DMODEL);
    transpose_h<<<dim3(4,  32), dim3(32, 8)>>>(Wkv, WkvT, DMODEL, 2 * DHEAD);
    transpose_h<<<dim3(32, 32), dim3(32, 8)>>>(Wc,  WcT,  DMODEL, DMODEL);

    // kvp partials = kv @ Wkv, split-K=4 (4096 x 128 x 256 each)
    gemm_f16<0><<<dim3(1, 32, NSPLIT), 128, GF16_SMEM_BYTES>>>(
        kvh, WkvT, kvp, L_TOK, 2 * DHEAD, DMODEL, DMODEL / NSPLIT, 1.0f);
    // K_eff fp16 + V_eff^T fp16 (chunk sums over splits)
    build_eff<<<(WCHUNK * DHEAD + 255) / 256, 256>>>(kvp, keff, vt);
    // qp = (q @ Wq) * log2e / 8, fp16 output (exp becomes bare ex2)
    gemm_f16<2><<<dim3(8, 32, 1), 128, GF16_SMEM_BYTES>>>(
        qh, WqT, qph, L_TOK, DMODEL, DMODEL, DMODEL, 0.125f * LOG2E);
    // attention: Q[65536,64] fp16 vs shared K/V[1536,64] fp16 -> fp16 ctx
    attn_fp16<<<NQROW / 128, 128, ATTN_SMEM_BYTES>>>(qph, keff, vt, ctxh);
    // out = ctx @ Wc (fp16 x fp16 -> fp32)
    gemm_f16<0><<<dim3(8, 32, 1), 128, GF16_SMEM_BYTES>>>(
        ctxh, WcT, out, L_TOK, DMODEL, DMODEL, DMODEL, 1.0f);
}